// round 12
// baseline (speedup 1.0000x reference)
#include <cuda_runtime.h>
#include <cstdint>
#include <cstddef>

typedef unsigned long long ull;

// 2-layer LSTM, B=512 T=1024 I=80 H=160, fp32, persistent 8-CTA-cluster kernel.
// 16 clusters x 8 ranks; cluster owns 32 batch (lanes), rank owns 20 h-rows
// (80 gate rows/layer), weight slices SMEM-resident. h replicated per rank as
// k-pair float2 layout, refreshed via st.shared::cluster.b64.
// 4 DSMEM mbarriers/step: C0/C1 consumed (count 80, lane-0 per warp, arrive
// immediately after the reading matmul), R0/R1 published (count 8, tid0 after
// __syncthreads). Every wait sits behind independent work.

#define HDIM   160
#define IDIM   80
#define TSTEPS 1024
#define CLUSTER 8
#define HS 20          // h rows per rank
#define GS 80          // gate rows per rank
#define NB 32          // batch per cluster (= lanes)
#define NTH 320        // 10 warps; warp w owns rows {2w,2w+1} of each quarter
#define NCLUS 16
#define GRIDN (NCLUS*CLUSTER)

// shared memory layout (float offsets)
#define OFF_W0   0        // W_hh0 slice [GS][HDIM]
#define OFF_WH1  12800    // W_hh1 slice [GS][HDIM]
#define OFF_WI1  25600    // W_ih1 slice [GS][HDIM]
#define OFF_WI0  38400    // W_ih0 slice [GS][IDIM]
#define OFF_HP0  44800    // h0 replica as k-pairs [80][NB] (ull)
#define OFF_HP1  49920    // h1 replica as k-pairs [80][NB] (ull)
#define OFF_XS   55040    // x tile as k-pairs [40][NB] (ull)
#define OFF_B0   57600    // fused bias layer0 slice [GS]
#define OFF_B1   57680    // fused bias layer1 slice [GS]
#define OFF_WOUT 57760    // W_out [HDIM]
#define OFF_BOUT 57920
#define OFF_MBAR 57928    // 4 mbarriers (u64), byte 231712, 8B aligned
#define SMEM_FLOATS 57936
#define SMEM_BYTES (SMEM_FLOATS*4)   // 231744 B <= 232448

// mbarrier byte offsets from smem base
#define MB_C0 (OFF_MBAR*4 + 0)   // h0(t-1) reads done (count 80)
#define MB_R0 (OFF_MBAR*4 + 8)   // h0(t) published    (count 8)
#define MB_C1 (OFF_MBAR*4 + 16)  // h1(t-1) reads done (count 80)
#define MB_R1 (OFF_MBAR*4 + 24)  // h1(t) published    (count 8)

__device__ __forceinline__ uint32_t smem_u32(const void* p){
    uint32_t a;
    asm("{ .reg .u64 t; cvta.to.shared.u64 t, %1; cvt.u32.u64 %0, t; }"
        : "=r"(a) : "l"(p));
    return a;
}
__device__ __forceinline__ uint32_t mapa_rank(uint32_t addr, uint32_t r){
    uint32_t d;
    asm("mapa.shared::cluster.u32 %0, %1, %2;" : "=r"(d) : "r"(addr), "r"(r));
    return d;
}
__device__ __forceinline__ void st_cluster_b64(uint32_t addr, ull v){
    asm volatile("st.shared::cluster.b64 [%0], %1;" :: "r"(addr), "l"(v));
}
__device__ __forceinline__ uint32_t ctarank(){
    uint32_t r; asm("mov.u32 %0, %%cluster_ctarank;" : "=r"(r)); return r;
}
__device__ __forceinline__ void mbar_init(uint32_t addr, uint32_t cnt){
    asm volatile("mbarrier.init.shared.b64 [%0], %1;" :: "r"(addr), "r"(cnt)
                 : "memory");
}
// arrive (release, cluster scope) on the same-offset barrier in every rank
__device__ __forceinline__ void mbar_arrive_all(uint32_t local_addr){
    #pragma unroll
    for (uint32_t r = 0; r < CLUSTER; r++){
        uint32_t ra = mapa_rank(local_addr, r);
        asm volatile(
            "mbarrier.arrive.release.cluster.shared::cluster.b64 _, [%0];"
            :: "r"(ra) : "memory");
    }
}
// wait on LOCAL barrier for phase of given parity (acquire, cluster scope)
__device__ __forceinline__ void mbar_wait(uint32_t addr, uint32_t parity){
    uint32_t done;
    asm volatile(
        "{ .reg .pred p;\n\t"
        "mbarrier.try_wait.parity.acquire.cluster.shared::cta.b64 p, [%1], %2;\n\t"
        "selp.b32 %0, 1, 0, p; }"
        : "=r"(done) : "r"(addr), "r"(parity) : "memory");
    while (!done){
        asm volatile(
            "{ .reg .pred p;\n\t"
            "mbarrier.try_wait.parity.acquire.cluster.shared::cta.b64 p, [%1], %2, 0x989680;\n\t"
            "selp.b32 %0, 1, 0, p; }"
            : "=r"(done) : "r"(addr), "r"(parity) : "memory");
    }
}

// packed fp32x2 FMA: a = b*c + a (lanewise, exact fp32)
__device__ __forceinline__ void ffma2(ull &a, ull b, ull c){
    asm("fma.rn.f32x2 %0, %1, %2, %0;" : "+l"(a) : "l"(b), "l"(c));
}
__device__ __forceinline__ ull pack2(float lo, float hi){
    ull r; asm("mov.b64 %0, {%1,%2};" : "=l"(r) : "f"(lo), "f"(hi)); return r;
}
__device__ __forceinline__ float sum2(ull v){
    float lo, hi; asm("mov.b64 {%0,%1}, %2;" : "=f"(lo), "=f"(hi) : "l"(v));
    return lo + hi;
}
__device__ __forceinline__ float sigm(float x){
    return __fdividef(1.0f, 1.0f + __expf(-x));
}
__device__ __forceinline__ float tanhfast(float x){
    return 2.0f*__fdividef(1.0f, 1.0f + __expf(-2.0f*x)) - 1.0f;
}

// acc[2q+p] (f32x2, even/odd-k partials) += W[(q*HS+r0+p)][:] . h[:]
// Software-pipelined: W (warp-uniform LDS.128) and h (lane LDS.64) for
// iteration kk+1 are loaded while iteration kk's FMAs issue.
template<int K>
__device__ __forceinline__ void mm8h(ull acc[8], const float* __restrict__ Wsm,
                                     int r0, const ull* __restrict__ hp){
    const ulonglong2* W[8];
    #pragma unroll
    for (int q = 0; q < 4; q++){
        W[2*q]   = reinterpret_cast<const ulonglong2*>(Wsm + (q*HS + r0    )*K);
        W[2*q+1] = reinterpret_cast<const ulonglong2*>(Wsm + (q*HS + r0 + 1)*K);
    }
    ull h01 = hp[0], h23 = hp[NB];
    ulonglong2 wv[8];
    #pragma unroll
    for (int r = 0; r < 8; r++) wv[r] = W[r][0];
    #pragma unroll 8
    for (int kk = 0; kk < K/4; kk++){
        ull n01 = 0, n23 = 0;
        ulonglong2 nw[8];
        if (kk + 1 < K/4){
            n01 = hp[(2*kk+2)*NB]; n23 = hp[(2*kk+3)*NB];
            #pragma unroll
            for (int r = 0; r < 8; r++) nw[r] = W[r][kk+1];
        }
        #pragma unroll
        for (int r = 0; r < 8; r++){
            ffma2(acc[r], wv[r].x, h01);
            ffma2(acc[r], wv[r].y, h23);
        }
        h01 = n01; h23 = n23;
        #pragma unroll
        for (int r = 0; r < 8; r++) wv[r] = nw[r];
    }
}

__global__ void __cluster_dims__(CLUSTER,1,1) __launch_bounds__(NTH,1)
lstm2_kernel(const float* __restrict__ x,
             const float* __restrict__ Wih0, const float* __restrict__ Whh0,
             const float* __restrict__ bih0, const float* __restrict__ bhh0,
             const float* __restrict__ Wih1, const float* __restrict__ Whh1,
             const float* __restrict__ bih1, const float* __restrict__ bhh1,
             const float* __restrict__ Wout, const float* __restrict__ bout,
             float* __restrict__ out)
{
    extern __shared__ float sm[];
    const int tid  = threadIdx.x;
    const int lane = tid & 31;
    const int w    = tid >> 5;        // 0..9
    const int r0   = 2*w;             // local rows r0, r0+1 per quarter
    const uint32_t rank = ctarank();
    const int cidx = blockIdx.x / CLUSTER;
    const int b0g  = cidx * NB;
    const int hb   = (int)rank * HS;
    const uint32_t smb = smem_u32(sm);

    // ---- persistent weight slices -> SMEM ----
    for (int idx = tid; idx < GS*HDIM; idx += NTH){
        int lr = idx / HDIM, k = idx - lr*HDIM;
        int q = lr / HS, j = lr - q*HS;
        int grow = q*HDIM + hb + j;           // pytorch gate order i,f,g,o
        sm[OFF_W0  + idx] = Whh0[grow*HDIM + k];
        sm[OFF_WH1 + idx] = Whh1[grow*HDIM + k];
        sm[OFF_WI1 + idx] = Wih1[grow*HDIM + k];
    }
    for (int idx = tid; idx < GS*IDIM; idx += NTH){
        int lr = idx / IDIM, k = idx - lr*IDIM;
        int q = lr / HS, j = lr - q*HS;
        int grow = q*HDIM + hb + j;
        sm[OFF_WI0 + idx] = Wih0[grow*IDIM + k];
    }
    for (int idx = tid; idx < GS; idx += NTH){
        int q = idx / HS, j = idx - q*HS;
        int grow = q*HDIM + hb + j;
        sm[OFF_B0 + idx] = bih0[grow] + bhh0[grow];
        sm[OFF_B1 + idx] = bih1[grow] + bhh1[grow];
    }
    for (int idx = tid; idx < HDIM; idx += NTH) sm[OFF_WOUT + idx] = Wout[idx];
    if (tid == 0) sm[OFF_BOUT] = bout[0];
    for (int idx = tid; idx < HDIM*NB; idx += NTH){
        sm[OFF_HP0 + idx] = 0.0f;
        sm[OFF_HP1 + idx] = 0.0f;
    }
    if (tid == 0){
        mbar_init(smb + MB_C0, CLUSTER*10);   // lane-0 of each warp, 8 ranks
        mbar_init(smb + MB_R0, CLUSTER);
        mbar_init(smb + MB_C1, CLUSTER*10);
        mbar_init(smb + MB_R1, CLUSTER);
    }
    float c0a = 0.f, c0b = 0.f, c1a = 0.f, c1b = 0.f;

    // x addressing: 8 elements/thread, fixed (b,i) per slot; xs is k-paired
    const float* xg = x + (size_t)b0g * TSTEPS * IDIM;
    const float* gptr[8]; int xo[8];
    #pragma unroll
    for (int u = 0; u < 8; u++){
        int idx = tid + u*NTH;                 // 0..2559
        int b = idx / IDIM, i = idx - b*IDIM;
        gptr[u] = xg + (size_t)b*TSTEPS*IDIM + i;
        xo[u]   = OFF_XS + ((i >> 1)*NB + b)*2 + (i & 1);
    }
    // stage x(0) before the cluster barrier
    #pragma unroll
    for (int u = 0; u < 8; u++) sm[xo[u]] = gptr[u][0];

    __syncthreads();
    // inits + zeroed replicas + x(0) visible cluster-wide
    asm volatile("barrier.cluster.arrive.aligned;" ::: "memory");
    asm volatile("barrier.cluster.wait.aligned;"   ::: "memory");
    // prime R1 phase 0 so wait R1(t-1) at t=0 completes immediately
    if (tid == 0) mbar_arrive_all(smb + MB_R1);

    // pair slot this warp produces: pair index rank*10 + w, element = lane
    const uint32_t o0 = smem_u32(reinterpret_cast<ull*>(&sm[OFF_HP0])
                                 + ((int)rank*10 + w)*NB + lane);
    const uint32_t o1 = smem_u32(reinterpret_cast<ull*>(&sm[OFF_HP1])
                                 + ((int)rank*10 + w)*NB + lane);
    uint32_t ad0[CLUSTER], ad1[CLUSTER];
    #pragma unroll
    for (uint32_t r = 0; r < CLUSTER; r++){
        ad0[r] = mapa_rank(o0, r);
        ad1[r] = mapa_rank(o1, r);
    }

    float b0r[8], b1r[8];
    #pragma unroll
    for (int q = 0; q < 4; q++){
        b0r[2*q]   = sm[OFF_B0 + q*HS + r0];
        b0r[2*q+1] = sm[OFF_B0 + q*HS + r0 + 1];
        b1r[2*q]   = sm[OFF_B1 + q*HS + r0];
        b1r[2*q+1] = sm[OFF_B1 + q*HS + r0 + 1];
    }

    const ull* hp0 = reinterpret_cast<const ull*>(&sm[OFF_HP0]) + lane;
    const ull* hp1 = reinterpret_cast<const ull*>(&sm[OFF_HP1]) + lane;
    const ull* xsp = reinterpret_cast<const ull*>(&sm[OFF_XS])  + lane;
    const ull* wo  = reinterpret_cast<const ull*>(&sm[OFF_WOUT]);
    const float boutv = bout[0];
    float* const orow = out + (size_t)(b0g + lane)*TSTEPS;

    for (int t = 0; t < TSTEPS; t++){
        const uint32_t par = (uint32_t)(t & 1);

        // prefetch x(t+1) into registers (LDG in flight through segment a-e)
        float xv[8];
        if (t + 1 < TSTEPS){
            #pragma unroll
            for (int u = 0; u < 8; u++) xv[u] = gptr[u][(size_t)(t+1)*IDIM];
        }

        // a: layer-0 recurrent, reads h0(t-1)
        ull acc[8];
        #pragma unroll
        for (int r = 0; r < 8; r++) acc[r] = pack2(b0r[r], 0.f);
        mm8h<HDIM>(acc, &sm[OFF_W0], r0, hp0);
        if (lane == 0) mbar_arrive_all(smb + MB_C0);   // EARLY arrive

        // b: x-projection (xs staged at f of step t-1) + activations
        mm8h<IDIM>(acc, &sm[OFF_WI0], r0, xsp);
        float hn0a, hn0b;
        {
            float gi = sigm(sum2(acc[0])), gf = sigm(sum2(acc[2]));
            float gg = tanhfast(sum2(acc[4])), go = sigm(sum2(acc[6]));
            c0a = gf*c0a + gi*gg;  hn0a = go*tanhfast(c0a);
            gi = sigm(sum2(acc[1])); gf = sigm(sum2(acc[3]));
            gg = tanhfast(sum2(acc[5])); go = sigm(sum2(acc[7]));
            c0b = gf*c0b + gi*gg;  hn0b = go*tanhfast(c0b);
        }

        // c: publish h0(t)
        mbar_wait(smb + MB_C0, par);       // all ranks done reading h0(t-1)
        {
            ull hv = pack2(hn0a, hn0b);
            #pragma unroll
            for (uint32_t r = 0; r < CLUSTER; r++) st_cluster_b64(ad0[r], hv);
        }
        __syncthreads();
        if (tid == 0) mbar_arrive_all(smb + MB_R0);

        // d: h1(t-1) ready (published at h of step t-1; long overlap)
        mbar_wait(smb + MB_R1, par);
        if (w == 0 && t > 0){               // output head for t-1
            ull s0 = pack2(boutv, 0.f), s1 = 0, s2 = 0, s3 = 0;
            #pragma unroll 10
            for (int p = 0; p < HDIM/2; p += 4){
                ffma2(s0, wo[p  ], hp1[(p  )*NB]);
                ffma2(s1, wo[p+1], hp1[(p+1)*NB]);
                ffma2(s2, wo[p+2], hp1[(p+2)*NB]);
                ffma2(s3, wo[p+3], hp1[(p+3)*NB]);
            }
            float y = (sum2(s0) + sum2(s1)) + (sum2(s2) + sum2(s3));
            orow[t-1] = fmaxf(y, 0.0f);
        }

        // e: layer-1 recurrent, reads h1(t-1)
        ull a1c[8];
        #pragma unroll
        for (int r = 0; r < 8; r++) a1c[r] = pack2(b1r[r], 0.f);
        mm8h<HDIM>(a1c, &sm[OFF_WH1], r0, hp1);
        if (lane == 0) mbar_arrive_all(smb + MB_C1);   // EARLY arrive

        // f: stage x(t+1) (WAR vs b(t) via c's syncthreads; visible to
        //    b(t+1) via h's syncthreads below)
        if (t + 1 < TSTEPS){
            #pragma unroll
            for (int u = 0; u < 8; u++) sm[xo[u]] = xv[u];
        }

        // g: h0(t) visible -> W_ih1 matmul + activations
        mbar_wait(smb + MB_R0, par);
        mm8h<HDIM>(a1c, &sm[OFF_WI1], r0, hp0);
        float hn1a, hn1b;
        {
            float gi = sigm(sum2(a1c[0])), gf = sigm(sum2(a1c[2]));
            float gg = tanhfast(sum2(a1c[4])), go = sigm(sum2(a1c[6]));
            c1a = gf*c1a + gi*gg;  hn1a = go*tanhfast(c1a);
            gi = sigm(sum2(a1c[1])); gf = sigm(sum2(a1c[3]));
            gg = tanhfast(sum2(a1c[5])); go = sigm(sum2(a1c[7]));
            c1b = gf*c1b + gi*gg;  hn1b = go*tanhfast(c1b);
        }

        // h: publish h1(t)
        mbar_wait(smb + MB_C1, par);       // all ranks done reading h1(t-1)
        {
            ull hv = pack2(hn1a, hn1b);
            #pragma unroll
            for (uint32_t r = 0; r < CLUSTER; r++) st_cluster_b64(ad1[r], hv);
        }
        __syncthreads();
        if (tid == 0) mbar_arrive_all(smb + MB_R1);
    }

    // final output head: y(T-1) after h1(T-1) published
    mbar_wait(smb + MB_R1, (uint32_t)(TSTEPS & 1));
    if (w == 0){
        ull s0 = pack2(boutv, 0.f), s1 = 0, s2 = 0, s3 = 0;
        #pragma unroll 10
        for (int p = 0; p < HDIM/2; p += 4){
            ffma2(s0, wo[p  ], hp1[(p  )*NB]);
            ffma2(s1, wo[p+1], hp1[(p+1)*NB]);
            ffma2(s2, wo[p+2], hp1[(p+2)*NB]);
            ffma2(s3, wo[p+3], hp1[(p+3)*NB]);
        }
        float y = (sum2(s0) + sum2(s1)) + (sum2(s2) + sum2(s3));
        orow[TSTEPS-1] = fmaxf(y, 0.0f);
    }
    // keep cluster resident until all ranks finish (writers target peer SMEM)
    asm volatile("barrier.cluster.arrive.aligned;" ::: "memory");
    asm volatile("barrier.cluster.wait.aligned;"   ::: "memory");
}

extern "C" void kernel_launch(void* const* d_in, const int* in_sizes, int n_in,
                              void* d_out, int out_size) {
    (void)in_sizes; (void)n_in; (void)out_size;
    const float* x    = (const float*)d_in[0];
    const float* Wih0 = (const float*)d_in[1];
    const float* Whh0 = (const float*)d_in[2];
    const float* bih0 = (const float*)d_in[3];
    const float* bhh0 = (const float*)d_in[4];
    const float* Wih1 = (const float*)d_in[5];
    const float* Whh1 = (const float*)d_in[6];
    const float* bih1 = (const float*)d_in[7];
    const float* bhh1 = (const float*)d_in[8];
    const float* Wout = (const float*)d_in[9];
    const float* bout = (const float*)d_in[10];
    float* out = (float*)d_out;

    cudaFuncSetAttribute(lstm2_kernel,
                         cudaFuncAttributeMaxDynamicSharedMemorySize, SMEM_BYTES);
    lstm2_kernel<<<GRIDN, NTH, SMEM_BYTES>>>(x, Wih0, Whh0, bih0, bhh0,
                                             Wih1, Whh1, bih1, bhh1,
                                             Wout, bout, out);
}

// round 13
// speedup vs baseline: 1.0830x; 1.0830x over previous
#include <cuda_runtime.h>
#include <cstdint>
#include <cstddef>

typedef unsigned long long ull;

// 2-layer LSTM, B=512 T=1024 I=80 H=160, fp32.
// Kernel 1 (xproj): X0[t][row][b] = x @ W_ih0^T + b_ih0 + b_hh0  (batch GEMM)
// Kernel 2 (lstm2): persistent 8-CTA-cluster recurrence. 16 clusters x 8
//   ranks; cluster owns 32 batch (lanes), rank owns 20 h-rows (80 gate rows
//   per layer). W_hh0/W_ih1/W_hh1 slices SMEM-resident. h replicated per rank
//   (k-pair float2); h0 double-buffered. ONLY 2 rendezvous per step (R0,R1,
//   count 80, per-warp store -> arrive.release), no consumed barriers, no
//   __syncthreads in the loop. W_hh1.h1(t-1) ordered before h0 publish so R0
//   transitively covers all WAR hazards.

#define HDIM   160
#define IDIM   80
#define TSTEPS 1024
#define BATCH  512
#define CLUSTER 8
#define HS 20
#define GS 80
#define NB 32
#define NTH 320
#define NCLUS 16
#define GRIDN (NCLUS*CLUSTER)

// X0 scratch: [t][640 rows][512 b]
__device__ float g_X0[(size_t)TSTEPS * 640 * BATCH];

// ---- lstm2 shared layout (float offsets) ----
#define OFF_W0   0        // W_hh0 slice [GS][HDIM]
#define OFF_WH1  12800    // W_hh1 slice [GS][HDIM]
#define OFF_WI1  25600    // W_ih1 slice [GS][HDIM]
#define OFF_H0A  38400    // h0 buf0, k-pairs [80][NB] (ull) = 5120 floats
#define OFF_H0B  43520    // h0 buf1
#define OFF_H1   48640    // h1 (single buffer)
#define OFF_WOUT 53760    // W_out [160]
#define OFF_B1   53920    // fused bias layer1 slice [GS]
#define OFF_MBAR 54000    // 2 mbarriers (u64); byte 216000, 8B aligned
#define SMEM_FLOATS 54008
#define SMEM_BYTES (SMEM_FLOATS*4)   // 216032 B

#define MB_R0 (OFF_MBAR*4 + 0)   // h0(t) published (count 80)
#define MB_R1 (OFF_MBAR*4 + 8)   // h1(t) published (count 80)

__device__ __forceinline__ uint32_t smem_u32(const void* p){
    uint32_t a;
    asm("{ .reg .u64 t; cvta.to.shared.u64 t, %1; cvt.u32.u64 %0, t; }"
        : "=r"(a) : "l"(p));
    return a;
}
__device__ __forceinline__ uint32_t mapa_rank(uint32_t addr, uint32_t r){
    uint32_t d;
    asm("mapa.shared::cluster.u32 %0, %1, %2;" : "=r"(d) : "r"(addr), "r"(r));
    return d;
}
__device__ __forceinline__ void st_cluster_b64(uint32_t addr, ull v){
    asm volatile("st.shared::cluster.b64 [%0], %1;" :: "r"(addr), "l"(v));
}
__device__ __forceinline__ uint32_t ctarank(){
    uint32_t r; asm("mov.u32 %0, %%cluster_ctarank;" : "=r"(r)); return r;
}
__device__ __forceinline__ void mbar_init(uint32_t addr, uint32_t cnt){
    asm volatile("mbarrier.init.shared.b64 [%0], %1;" :: "r"(addr), "r"(cnt)
                 : "memory");
}
__device__ __forceinline__ void mbar_arrive_all(uint32_t local_addr){
    #pragma unroll
    for (uint32_t r = 0; r < CLUSTER; r++){
        uint32_t ra = mapa_rank(local_addr, r);
        asm volatile(
            "mbarrier.arrive.release.cluster.shared::cluster.b64 _, [%0];"
            :: "r"(ra) : "memory");
    }
}
__device__ __forceinline__ void mbar_wait(uint32_t addr, uint32_t parity){
    uint32_t done;
    asm volatile(
        "{ .reg .pred p;\n\t"
        "mbarrier.try_wait.parity.acquire.cluster.shared::cta.b64 p, [%1], %2;\n\t"
        "selp.b32 %0, 1, 0, p; }"
        : "=r"(done) : "r"(addr), "r"(parity) : "memory");
    while (!done){
        asm volatile(
            "{ .reg .pred p;\n\t"
            "mbarrier.try_wait.parity.acquire.cluster.shared::cta.b64 p, [%1], %2, 0x989680;\n\t"
            "selp.b32 %0, 1, 0, p; }"
            : "=r"(done) : "r"(addr), "r"(parity) : "memory");
    }
}

__device__ __forceinline__ void ffma2(ull &a, ull b, ull c){
    asm("fma.rn.f32x2 %0, %1, %2, %0;" : "+l"(a) : "l"(b), "l"(c));
}
__device__ __forceinline__ ull pack2(float lo, float hi){
    ull r; asm("mov.b64 %0, {%1,%2};" : "=l"(r) : "f"(lo), "f"(hi)); return r;
}
__device__ __forceinline__ float sum2(ull v){
    float lo, hi; asm("mov.b64 {%0,%1}, %2;" : "=f"(lo), "=f"(hi) : "l"(v));
    return lo + hi;
}
__device__ __forceinline__ float sigm(float x){
    return __fdividef(1.0f, 1.0f + __expf(-x));
}
__device__ __forceinline__ float tanhfast(float x){
    return 2.0f*__fdividef(1.0f, 1.0f + __expf(-2.0f*x)) - 1.0f;
}

// acc[2q+p] (f32x2, even/odd-k partials) += W[(q*HS+r0+p)][:] . h[:]
// W warp-uniform LDS.128; h lane LDS.64; next iter's loads pipelined.
template<int K>
__device__ __forceinline__ void mm8h(ull acc[8], const float* __restrict__ Wsm,
                                     int r0, const ull* __restrict__ hp){
    const ulonglong2* W[8];
    #pragma unroll
    for (int q = 0; q < 4; q++){
        W[2*q]   = reinterpret_cast<const ulonglong2*>(Wsm + (q*HS + r0    )*K);
        W[2*q+1] = reinterpret_cast<const ulonglong2*>(Wsm + (q*HS + r0 + 1)*K);
    }
    ull h01 = hp[0], h23 = hp[NB];
    ulonglong2 wv[8];
    #pragma unroll
    for (int r = 0; r < 8; r++) wv[r] = W[r][0];
    #pragma unroll 8
    for (int kk = 0; kk < K/4; kk++){
        ull n01 = 0, n23 = 0;
        ulonglong2 nw[8];
        if (kk + 1 < K/4){
            n01 = hp[(2*kk+2)*NB]; n23 = hp[(2*kk+3)*NB];
            #pragma unroll
            for (int r = 0; r < 8; r++) nw[r] = W[r][kk+1];
        }
        #pragma unroll
        for (int r = 0; r < 8; r++){
            ffma2(acc[r], wv[r].x, h01);
            ffma2(acc[r], wv[r].y, h23);
        }
        h01 = n01; h23 = n23;
        #pragma unroll
        for (int r = 0; r < 8; r++) wv[r] = nw[r];
    }
}

// ============ kernel 1: X0 = x @ W_ih0^T + bias ============
#define XP_THREADS 256
#define XP_LD 132   // padded smem row stride

__global__ __launch_bounds__(XP_THREADS)
void xproj_kernel(const float* __restrict__ x,
                  const float* __restrict__ Wih0,
                  const float* __restrict__ bih0,
                  const float* __restrict__ bhh0)
{
    extern __shared__ float s[];
    float* WT = s;                 // [80][XP_LD]  (k-major, row in col)
    float* XT = s + IDIM*XP_LD;    // [80][XP_LD]  (k-major, batch in col)
    const int t = blockIdx.z;
    const int rowbase = blockIdx.y * 128;
    const int bbase   = blockIdx.x * 128;

    for (int idx = threadIdx.x; idx < 128*IDIM; idx += XP_THREADS){
        int r = idx / IDIM, k = idx - r*IDIM;
        WT[k*XP_LD + r] = Wih0[(rowbase + r)*IDIM + k];
    }
    for (int idx = threadIdx.x; idx < 128*IDIM; idx += XP_THREADS){
        int b = idx / IDIM, k = idx - b*IDIM;
        XT[k*XP_LD + b] = x[(size_t)(bbase + b)*(TSTEPS*IDIM)
                            + (size_t)t*IDIM + k];
    }
    __syncthreads();

    const int brow = threadIdx.x >> 4;   // 0..15
    const int bcol = threadIdx.x & 15;   // 0..15
    float acc[8][8] = {};
    for (int k = 0; k < IDIM; k++){
        float wr[8], xr[8];
        #pragma unroll
        for (int i = 0; i < 8; i++) wr[i] = WT[k*XP_LD + brow + 16*i];
        #pragma unroll
        for (int j = 0; j < 8; j++) xr[j] = XT[k*XP_LD + bcol + 16*j];
        #pragma unroll
        for (int i = 0; i < 8; i++)
            #pragma unroll
            for (int j = 0; j < 8; j++)
                acc[i][j] += wr[i]*xr[j];
    }
    #pragma unroll
    for (int i = 0; i < 8; i++){
        int row = rowbase + brow + 16*i;
        float bias = bih0[row] + bhh0[row];
        float* dst = g_X0 + ((size_t)t*640 + row)*BATCH + bbase;
        #pragma unroll
        for (int j = 0; j < 8; j++)
            dst[bcol + 16*j] = acc[i][j] + bias;
    }
}

// ============ kernel 2: recurrence ============
__global__ void __cluster_dims__(CLUSTER,1,1) __launch_bounds__(NTH,1)
lstm2_kernel(const float* __restrict__ Whh0,
             const float* __restrict__ Wih1, const float* __restrict__ Whh1,
             const float* __restrict__ bih1, const float* __restrict__ bhh1,
             const float* __restrict__ Wout, const float* __restrict__ bout,
             float* __restrict__ out)
{
    extern __shared__ float sm[];
    const int tid  = threadIdx.x;
    const int lane = tid & 31;
    const int w    = tid >> 5;        // 0..9
    const int r0   = 2*w;
    const uint32_t rank = ctarank();
    const int cidx = blockIdx.x / CLUSTER;
    const int b0g  = cidx * NB;
    const int hb   = (int)rank * HS;
    const uint32_t smb = smem_u32(sm);

    // persistent weight slices
    for (int idx = tid; idx < GS*HDIM; idx += NTH){
        int lr = idx / HDIM, k = idx - lr*HDIM;
        int q = lr / HS, j = lr - q*HS;
        int grow = q*HDIM + hb + j;           // pytorch gate order i,f,g,o
        sm[OFF_W0  + idx] = Whh0[grow*HDIM + k];
        sm[OFF_WH1 + idx] = Whh1[grow*HDIM + k];
        sm[OFF_WI1 + idx] = Wih1[grow*HDIM + k];
    }
    for (int idx = tid; idx < GS; idx += NTH){
        int q = idx / HS, j = idx - q*HS;
        int grow = q*HDIM + hb + j;
        sm[OFF_B1 + idx] = bih1[grow] + bhh1[grow];
    }
    for (int idx = tid; idx < HDIM; idx += NTH) sm[OFF_WOUT + idx] = Wout[idx];
    for (int idx = tid; idx < 3*HDIM*NB; idx += NTH) sm[OFF_H0A + idx] = 0.0f;
    if (tid == 0){
        mbar_init(smb + MB_R0, CLUSTER*10);
        mbar_init(smb + MB_R1, CLUSTER*10);
    }
    float c0a = 0.f, c0b = 0.f, c1a = 0.f, c1b = 0.f;
    __syncthreads();
    asm volatile("barrier.cluster.arrive.aligned;" ::: "memory");
    asm volatile("barrier.cluster.wait.aligned;"   ::: "memory");
    // prime R1 phase 0 (h1(-1)=0 already staged): every warp lane0
    if (lane == 0) mbar_arrive_all(smb + MB_R1);

    // store slots (pair index rank*10+w, element lane) in both h0 bufs + h1
    const uint32_t oA = smem_u32(reinterpret_cast<ull*>(&sm[OFF_H0A])
                                 + ((int)rank*10 + w)*NB + lane);
    const uint32_t oB = smem_u32(reinterpret_cast<ull*>(&sm[OFF_H0B])
                                 + ((int)rank*10 + w)*NB + lane);
    const uint32_t o1 = smem_u32(reinterpret_cast<ull*>(&sm[OFF_H1])
                                 + ((int)rank*10 + w)*NB + lane);
    uint32_t adA[CLUSTER], adB[CLUSTER], ad1[CLUSTER];
    #pragma unroll
    for (uint32_t r = 0; r < CLUSTER; r++){
        adA[r] = mapa_rank(oA, r);
        adB[r] = mapa_rank(oB, r);
        ad1[r] = mapa_rank(o1, r);
    }

    float b1r[8];
    #pragma unroll
    for (int q = 0; q < 4; q++){
        b1r[2*q]   = sm[OFF_B1 + q*HS + r0];
        b1r[2*q+1] = sm[OFF_B1 + q*HS + r0 + 1];
    }

    // X0 row pointers: row (u>>1)*HDIM + hb + 2w + (u&1), col b0g+lane
    const float* xp[8];
    #pragma unroll
    for (int u = 0; u < 8; u++){
        int grow = (u >> 1)*HDIM + hb + r0 + (u & 1);
        xp[u] = g_X0 + (size_t)grow*BATCH + b0g + lane;
    }

    const ull* h0A = reinterpret_cast<const ull*>(&sm[OFF_H0A]) + lane;
    const ull* h0B = reinterpret_cast<const ull*>(&sm[OFF_H0B]) + lane;
    const ull* hp1 = reinterpret_cast<const ull*>(&sm[OFF_H1])  + lane;
    const ull* wo  = reinterpret_cast<const ull*>(&sm[OFF_WOUT]);
    const float boutv = bout[0];
    float* const orow = out + (size_t)(b0g + lane)*TSTEPS;

    for (int t = 0; t < TSTEPS; t++){
        const uint32_t par = (uint32_t)(t & 1);
        const int p = t & 1;
        const ull* hp0_old = p ? h0A : h0B;   // buf (t-1)&1
        const ull* hp0_new = p ? h0B : h0A;   // buf t&1
        const uint32_t* adw = p ? adB : adA;

        // 1: LDG X0 gate seeds for step t (in flight through segment 2)
        float xg[8];
        #pragma unroll
        for (int u = 0; u < 8; u++) xg[u] = xp[u][(size_t)t*640*BATCH];

        // 2: layer-0 recurrent, reads h0(t-1)
        ull acc[8];
        #pragma unroll
        for (int r = 0; r < 8; r++) acc[r] = pack2(xg[r], 0.f);
        mm8h<HDIM>(acc, &sm[OFF_W0], r0, hp0_old);

        // 3: h1(t-1) ready (published at step t-1 end; hidden behind 2)
        mbar_wait(smb + MB_R1, par);

        // 4: output head for t-1 (reads h1(t-1); ordered before any h1(t)
        //    store via this warp's R0 arrive below)
        if (w == 0 && t > 0){
            ull s0 = pack2(boutv, 0.f), s1 = 0, s2 = 0, s3 = 0;
            #pragma unroll 10
            for (int pp = 0; pp < HDIM/2; pp += 4){
                ffma2(s0, wo[pp  ], hp1[(pp  )*NB]);
                ffma2(s1, wo[pp+1], hp1[(pp+1)*NB]);
                ffma2(s2, wo[pp+2], hp1[(pp+2)*NB]);
                ffma2(s3, wo[pp+3], hp1[(pp+3)*NB]);
            }
            float y = (sum2(s0) + sum2(s1)) + (sum2(s2) + sum2(s3));
            orow[t-1] = fmaxf(y, 0.0f);
        }

        // 5: layer-1 recurrent W_hh1 . h1(t-1) — MUST precede h0 publish
        ull a1c[8];
        #pragma unroll
        for (int r = 0; r < 8; r++) a1c[r] = pack2(b1r[r], 0.f);
        mm8h<HDIM>(a1c, &sm[OFF_WH1], r0, hp1);

        // 6: layer-0 activations
        float hn0a, hn0b;
        {
            float gi = sigm(sum2(acc[0])), gf = sigm(sum2(acc[2]));
            float gg = tanhfast(sum2(acc[4])), go = sigm(sum2(acc[6]));
            c0a = gf*c0a + gi*gg;  hn0a = go*tanhfast(c0a);
            gi = sigm(sum2(acc[1])); gf = sigm(sum2(acc[3]));
            gg = tanhfast(sum2(acc[5])); go = sigm(sum2(acc[7]));
            c0b = gf*c0b + gi*gg;  hn0b = go*tanhfast(c0b);
        }

        // 7: publish h0(t) -> buf t&1 (per-warp store + arrive.release)
        {
            ull hv = pack2(hn0a, hn0b);
            #pragma unroll
            for (uint32_t r = 0; r < CLUSTER; r++) st_cluster_b64(adw[r], hv);
        }
        if (lane == 0) mbar_arrive_all(smb + MB_R0);

        // 8: h0(t) visible everywhere
        mbar_wait(smb + MB_R0, par);

        // 9: W_ih1 . h0(t)
        mm8h<HDIM>(a1c, &sm[OFF_WI1], r0, hp0_new);

        // 10: layer-1 activations
        float hn1a, hn1b;
        {
            float gi = sigm(sum2(a1c[0])), gf = sigm(sum2(a1c[2]));
            float gg = tanhfast(sum2(a1c[4])), go = sigm(sum2(a1c[6]));
            c1a = gf*c1a + gi*gg;  hn1a = go*tanhfast(c1a);
            gi = sigm(sum2(a1c[1])); gf = sigm(sum2(a1c[3]));
            gg = tanhfast(sum2(a1c[5])); go = sigm(sum2(a1c[7]));
            c1b = gf*c1b + gi*gg;  hn1b = go*tanhfast(c1b);
        }

        // 11: publish h1(t) (single buffer; WAR covered by R0(t))
        {
            ull hv = pack2(hn1a, hn1b);
            #pragma unroll
            for (uint32_t r = 0; r < CLUSTER; r++) st_cluster_b64(ad1[r], hv);
        }
        if (lane == 0) mbar_arrive_all(smb + MB_R1);
    }

    // final head: h1(T-1) after last R1 completion (phase T, parity 0)
    mbar_wait(smb + MB_R1, (uint32_t)(TSTEPS & 1));
    if (w == 0){
        ull s0 = pack2(boutv, 0.f), s1 = 0, s2 = 0, s3 = 0;
        #pragma unroll 10
        for (int pp = 0; pp < HDIM/2; pp += 4){
            ffma2(s0, wo[pp  ], hp1[(pp  )*NB]);
            ffma2(s1, wo[pp+1], hp1[(pp+1)*NB]);
            ffma2(s2, wo[pp+2], hp1[(pp+2)*NB]);
            ffma2(s3, wo[pp+3], hp1[(pp+3)*NB]);
        }
        float y = (sum2(s0) + sum2(s1)) + (sum2(s2) + sum2(s3));
        orow[TSTEPS-1] = fmaxf(y, 0.0f);
    }
    asm volatile("barrier.cluster.arrive.aligned;" ::: "memory");
    asm volatile("barrier.cluster.wait.aligned;"   ::: "memory");
}

extern "C" void kernel_launch(void* const* d_in, const int* in_sizes, int n_in,
                              void* d_out, int out_size) {
    (void)in_sizes; (void)n_in; (void)out_size;
    const float* x    = (const float*)d_in[0];
    const float* Wih0 = (const float*)d_in[1];
    const float* Whh0 = (const float*)d_in[2];
    const float* bih0 = (const float*)d_in[3];
    const float* bhh0 = (const float*)d_in[4];
    const float* Wih1 = (const float*)d_in[5];
    const float* Whh1 = (const float*)d_in[6];
    const float* bih1 = (const float*)d_in[7];
    const float* bhh1 = (const float*)d_in[8];
    const float* Wout = (const float*)d_in[9];
    const float* bout = (const float*)d_in[10];
    float* out = (float*)d_out;

    const int xp_smem = 2*IDIM*XP_LD*4;  // 84480 B
    cudaFuncSetAttribute(xproj_kernel,
                         cudaFuncAttributeMaxDynamicSharedMemorySize, xp_smem);
    dim3 xg(BATCH/128, 640/128, TSTEPS);
    xproj_kernel<<<xg, XP_THREADS, xp_smem>>>(x, Wih0, bih0, bhh0);

    cudaFuncSetAttribute(lstm2_kernel,
                         cudaFuncAttributeMaxDynamicSharedMemorySize, SMEM_BYTES);
    lstm2_kernel<<<GRIDN, NTH, SMEM_BYTES>>>(Whh0, Wih1, Whh1,
                                             bih1, bhh1, Wout, bout, out);
}